// round 8
// baseline (speedup 1.0000x reference)
#include <cuda_runtime.h>
#include <cuda_bf16.h>

// ---------------------------------------------------------------------------
// graph_encoder: B=16, N=1024, H=256, 4 heads (d=64), 2 layers.
// R7: ldmatrix fragment loads, no K-transpose, warp-per-row LN.
// ---------------------------------------------------------------------------

#define Bsz   16
#define Nn    1024
#define Hd    256
#define Ee    767
#define Rr    256
#define ROOTI 46
#define Mrows (Bsz * Nn)
#define XSZ   (Mrows * Hd)
#define H1SZ  (Mrows * 4 * Hd)
#define QKVSZ (Mrows * 3 * Hd)

__device__ float    g_x   [XSZ];
__device__ float    g_qkv [QKVSZ];   // [16384, 768] (q|k|v)
__device__ float    g_o   [XSZ];
__device__ float    g_t   [XSZ];
__device__ float    g_h2  [XSZ];
__device__ float    g_h1  [H1SZ];
__device__ float    g_wqkv[Hd * 3 * Hd];
__device__ unsigned g_adjb[Bsz * Nn * 32];

// ---------------------------------------------------------------------------
__device__ __forceinline__ unsigned packbf(float lo, float hi)
{
    unsigned u;
    asm("cvt.rn.bf16x2.f32 %0, %1, %2;" : "=r"(u) : "f"(hi), "f"(lo));
    return u;
}

#define BF16_MMA(d, a, b)                                                     \
    asm volatile(                                                             \
        "mma.sync.aligned.m16n8k16.row.col.f32.bf16.bf16.f32 "                \
        "{%0,%1,%2,%3},{%4,%5,%6,%7},{%8,%9},{%0,%1,%2,%3};"                  \
        : "+f"((d)[0]), "+f"((d)[1]), "+f"((d)[2]), "+f"((d)[3])              \
        : "r"((a)[0]), "r"((a)[1]), "r"((a)[2]), "r"((a)[3]),                 \
          "r"((b)[0]), "r"((b)[1]))

__device__ __forceinline__ void ldsm4(unsigned addr, unsigned* r)
{
    asm volatile("ldmatrix.sync.aligned.m8n8.x4.shared.b16 {%0,%1,%2,%3}, [%4];"
                 : "=r"(r[0]), "=r"(r[1]), "=r"(r[2]), "=r"(r[3]) : "r"(addr));
}
__device__ __forceinline__ void ldsm4t(unsigned addr, unsigned* r)
{
    asm volatile("ldmatrix.sync.aligned.m8n8.x4.trans.shared.b16 {%0,%1,%2,%3}, [%4];"
                 : "=r"(r[0]), "=r"(r[1]), "=r"(r[2]), "=r"(r[3]) : "r"(addr));
}

// ---------------------------------------------------------------------------
__global__ void embed_kernel(const int* __restrict__ ents,
                             const int* __restrict__ rels,
                             const float* __restrict__ ent_table,
                             const float* __restrict__ rel_table,
                             float* __restrict__ x)
{
    int bn = blockIdx.x;
    int b  = bn >> 10;
    int n  = bn & 1023;
    const float* src;
    if (n < Ee)            src = ent_table + (size_t)ents[b * Ee + n] * Hd;
    else if (n < Ee + Rr)  src = rel_table + (size_t)rels[b * Rr + (n - Ee)] * Hd;
    else                   src = rel_table + (size_t)ROOTI * Hd;
    x[(size_t)bn * Hd + threadIdx.x] = src[threadIdx.x];
}

// ---------------------------------------------------------------------------
__global__ void packw_kernel(const float* __restrict__ wq,
                             const float* __restrict__ wk,
                             const float* __restrict__ wv,
                             float* __restrict__ out)
{
    int i = blockIdx.x * blockDim.x + threadIdx.x;
    int k = i / 768, c = i - k * 768;
    float v;
    if (c < 256)      v = wq[k * 256 + c];
    else if (c < 512) v = wk[k * 256 + c - 256];
    else              v = wv[k * 256 + c - 512];
    out[i] = v;
}

// ---------------------------------------------------------------------------
__global__ void adjpack_kernel(const int* __restrict__ adj,
                               unsigned* __restrict__ adjb)
{
    int gw   = blockIdx.x * 8 + (threadIdx.x >> 5);
    int lane = threadIdx.x & 31;
    int row  = gw >> 5;
    int wrd  = gw & 31;
    int v = adj[((size_t)row << 10) + wrd * 32 + lane];
    unsigned m = __ballot_sync(0xffffffffu, v != 0);
    if (lane == 0) adjb[gw] = m;
}

// ---------------------------------------------------------------------------
// bf16 GEMM with ldmatrix. Block 128x128, 8 warps (2x4), warp 64x32, kstep 16.
// Smem: A [2][128][24] bf16 (48B rows), B [2][16][136] bf16 (272B rows).
// ---------------------------------------------------------------------------
#define GA_STG 6144            // 128*48 bytes
#define GB_STG 4352            // 16*272 bytes
#define GB_OFF (2 * GA_STG)

__global__ void __launch_bounds__(256, 2)
gemm_tc(const float* __restrict__ A,
        const float* __restrict__ W,
        float* __restrict__ C,
        int K, int lda, int ldb, int ldc,
        const float* __restrict__ bias,
        const float* __restrict__ alpha,
        int mode)
{
    __shared__ __align__(16) unsigned char smc[2 * GA_STG + 2 * GB_STG];
    unsigned sbase = (unsigned)__cvta_generic_to_shared(smc);

    int t    = threadIdx.x;
    int w    = t >> 5, lane = t & 31;
    int gid  = lane >> 2, tid4 = lane & 3;
    int wm0  = (w >> 2) * 64;
    int wn0  = (w & 3) * 32;
    int row0 = blockIdx.y << 7;
    int col0 = blockIdx.x << 7;

    int am  = t >> 1;            // A row, 0..127
    int ac  = (t & 1) * 8;       // A k offset 0/8
    int bk  = t >> 4;            // B k row, 0..15
    int bn  = (t & 15) * 8;      // B n offset

    const float* Ap = A + (size_t)(row0 + am) * lda + ac;
    const float* Bp = W + (size_t)bk * ldb + col0 + bn;

    // ldmatrix lane addresses (byte offsets inside a stage)
    int a_row = (lane & 7) + ((lane >> 3) & 1) * 8;
    int a_coff = (lane >> 4) * 16;
    int b_row = (lane & 7) + ((lane >> 3) & 1) * 8;

    {
        float4 a0 = *(const float4*)Ap;
        float4 a1 = *(const float4*)(Ap + 4);
        *(uint4*)(smc + am * 48 + ac * 2) =
            make_uint4(packbf(a0.x, a0.y), packbf(a0.z, a0.w),
                       packbf(a1.x, a1.y), packbf(a1.z, a1.w));
        float4 b0 = *(const float4*)Bp;
        float4 b1 = *(const float4*)(Bp + 4);
        *(uint4*)(smc + GB_OFF + bk * 272 + bn * 2) =
            make_uint4(packbf(b0.x, b0.y), packbf(b0.z, b0.w),
                       packbf(b1.x, b1.y), packbf(b1.z, b1.w));
    }
    __syncthreads();

    float acc[4][4][4] = {};
    int buf = 0;

    for (int k0 = 16; k0 <= K; k0 += 16) {
        float4 na0, na1, nb0, nb1;
        if (k0 < K) {
            na0 = *(const float4*)(Ap + k0);
            na1 = *(const float4*)(Ap + k0 + 4);
            nb0 = *(const float4*)(Bp + (size_t)k0 * ldb);
            nb1 = *(const float4*)(Bp + (size_t)k0 * ldb + 4);
        }
        {
            unsigned af[4][4], bfr[4][2];
#pragma unroll
            for (int np = 0; np < 2; np++) {
                unsigned r[4];
                unsigned addr = sbase + GB_OFF + buf * GB_STG + b_row * 272
                              + (wn0 + np * 16 + (lane >> 4) * 8) * 2;
                ldsm4t(addr, r);
                bfr[np * 2 + 0][0] = r[0]; bfr[np * 2 + 0][1] = r[1];
                bfr[np * 2 + 1][0] = r[2]; bfr[np * 2 + 1][1] = r[3];
            }
#pragma unroll
            for (int mt = 0; mt < 4; mt++) {
                unsigned addr = sbase + buf * GA_STG
                              + (wm0 + mt * 16 + a_row) * 48 + a_coff;
                ldsm4(addr, af[mt]);
            }
#pragma unroll
            for (int mt = 0; mt < 4; mt++)
#pragma unroll
                for (int nt = 0; nt < 4; nt++)
                    BF16_MMA(acc[mt][nt], af[mt], bfr[nt]);
        }
        if (k0 < K) {
            buf ^= 1;
            *(uint4*)(smc + buf * GA_STG + am * 48 + ac * 2) =
                make_uint4(packbf(na0.x, na0.y), packbf(na0.z, na0.w),
                           packbf(na1.x, na1.y), packbf(na1.z, na1.w));
            *(uint4*)(smc + GB_OFF + buf * GB_STG + bk * 272 + bn * 2) =
                make_uint4(packbf(nb0.x, nb0.y), packbf(nb0.z, nb0.w),
                           packbf(nb1.x, nb1.y), packbf(nb1.z, nb1.w));
            __syncthreads();
        }
    }

#pragma unroll
    for (int mt = 0; mt < 4; mt++) {
        int r0 = row0 + wm0 + mt * 16 + gid;
#pragma unroll
        for (int nt = 0; nt < 4; nt++) {
            int c = col0 + wn0 + nt * 8 + 2 * tid4;
            float v0 = acc[mt][nt][0], v1 = acc[mt][nt][1];
            float v2 = acc[mt][nt][2], v3 = acc[mt][nt][3];
            if (mode != 0) {
                float b0v = bias[c], b1v = bias[c + 1];
                v0 += b0v; v1 += b1v; v2 += b0v; v3 += b1v;
            }
            if (mode == 1) {
                float a0v = alpha[c], a1v = alpha[c + 1];
                v0 = v0 >= 0.f ? v0 : a0v * v0;
                v1 = v1 >= 0.f ? v1 : a1v * v1;
                v2 = v2 >= 0.f ? v2 : a0v * v2;
                v3 = v3 >= 0.f ? v3 : a1v * v3;
            }
            *(float2*)&C[(size_t)r0 * ldc + c]       = make_float2(v0, v1);
            *(float2*)&C[(size_t)(r0 + 8) * ldc + c] = make_float2(v2, v3);
        }
    }
}

// ---------------------------------------------------------------------------
// Fused flash attention with ldmatrix; K/V loaded straight from qkv.
// Smem (bytes): Q[128][72bf16] K[...] V[...] P[128][136bf16] red[1024 f32]
// ---------------------------------------------------------------------------
#define FQ_B 0
#define FK_B 18432
#define FV_B 36864
#define FP_B 55296
#define FR_B 90112
#define FL_SMEM (FR_B + 4096)

__global__ void __launch_bounds__(256, 2)
flash_attn(const float* __restrict__ qkv,
           const unsigned* __restrict__ adjb,
           const float* __restrict__ X,
           float* __restrict__ O)
{
    extern __shared__ __align__(16) unsigned char smc[];
    unsigned sbase = (unsigned)__cvta_generic_to_shared(smc);
    float* redm = (float*)(smc + FR_B);
    float* reds = redm + 512;

    int t = threadIdx.x;
    int w = t >> 5, lane = t & 31;
    int gid = lane >> 2, tid4 = lane & 3;
    int wm0 = (w >> 2) * 64;
    int wn0 = (w & 3) * 32;
    int wd0 = (w & 3) * 16;
    int z = blockIdx.y;
    int b = z >> 2, h = z & 3;
    int i0 = blockIdx.x << 7;

    // ldmatrix lane geometry
    int arow  = (lane & 7) + ((lane >> 3) & 1) * 8;   // A-frag row offset
    int acoff = (lane >> 4) * 16;                     // A-frag k byte offset
    int krow  = (lane >> 4) * 8 + (lane & 7);         // K B-frag row offset (j)
    int kcoff = ((lane >> 3) & 1) * 16;               // K B-frag d byte offset
    int vrow  = ((lane >> 3) & 1) * 8 + (lane & 7);   // V trans row offset (j)
    int vcoff = (wd0 + (lane >> 4) * 8) * 2;          // V trans d byte offset

    // ---- Q tile -> smem [i][d] bf16, once ----
    {
        int i  = t >> 1;
        int dh = (t & 1) * 32;
        const float* src = qkv + (size_t)(b * Nn + i0 + i) * 768 + h * 64 + dh;
        unsigned char* dst = smc + FQ_B + i * 144 + dh * 2;
#pragma unroll
        for (int c = 0; c < 32; c += 8) {
            float4 x0 = *(const float4*)(src + c);
            float4 x1 = *(const float4*)(src + c + 4);
            *(uint4*)(dst + c * 2) =
                make_uint4(packbf(x0.x, x0.y), packbf(x0.z, x0.w),
                           packbf(x1.x, x1.y), packbf(x1.z, x1.w));
        }
    }

    float m_st[8], l_st[8];
    float oac[4][2][4] = {};
#pragma unroll
    for (int s = 0; s < 8; s++) { m_st[s] = -1e4f; l_st[s] = 0.f; }

    for (int jt = 0; jt < 8; jt++) {
        int j0 = jt << 7;
        __syncthreads();

        // ---- K, V tiles -> smem [j][d] bf16 ----
        {
            int jj = t >> 1;
            int dh = (t & 1) * 32;
            const float* srck = qkv + (size_t)(b * Nn + j0 + jj) * 768 + 256 + h * 64 + dh;
            const float* srcv = srck + 256;
            unsigned char* dk = smc + FK_B + jj * 144 + dh * 2;
            unsigned char* dv = smc + FV_B + jj * 144 + dh * 2;
#pragma unroll
            for (int c = 0; c < 32; c += 8) {
                float4 x0 = *(const float4*)(srck + c);
                float4 x1 = *(const float4*)(srck + c + 4);
                *(uint4*)(dk + c * 2) =
                    make_uint4(packbf(x0.x, x0.y), packbf(x0.z, x0.w),
                               packbf(x1.x, x1.y), packbf(x1.z, x1.w));
                float4 y0 = *(const float4*)(srcv + c);
                float4 y1 = *(const float4*)(srcv + c + 4);
                *(uint4*)(dv + c * 2) =
                    make_uint4(packbf(y0.x, y0.y), packbf(y0.z, y0.w),
                               packbf(y1.x, y1.y), packbf(y1.z, y1.w));
            }
        }
        __syncthreads();

        // ---- S = Q @ K^T (128x128, d=64) ----
        float sac[4][4][4] = {};
#pragma unroll
        for (int ko = 0; ko < 64; ko += 16) {
            unsigned af[4][4], bfr[4][2];
#pragma unroll
            for (int jg = 0; jg < 2; jg++) {
                unsigned r[4];
                unsigned addr = sbase + FK_B + (wn0 + jg * 16 + krow) * 144
                              + ko * 2 + kcoff;
                ldsm4(addr, r);
                bfr[jg * 2 + 0][0] = r[0]; bfr[jg * 2 + 0][1] = r[1];
                bfr[jg * 2 + 1][0] = r[2]; bfr[jg * 2 + 1][1] = r[3];
            }
#pragma unroll
            for (int mt = 0; mt < 4; mt++) {
                unsigned addr = sbase + FQ_B + (wm0 + mt * 16 + arow) * 144
                              + ko * 2 + acoff;
                ldsm4(addr, af[mt]);
            }
#pragma unroll
            for (int mt = 0; mt < 4; mt++)
#pragma unroll
                for (int nt = 0; nt < 4; nt++)
                    BF16_MMA(sac[mt][nt], af[mt], bfr[nt]);
        }

        // ---- mask (bitpacked) + scale, per-row tile max ----
        int wq = (j0 + wn0) >> 5;
        float tmax[8];
#pragma unroll
        for (int s = 0; s < 8; s++) tmax[s] = -1e30f;
#pragma unroll
        for (int mt = 0; mt < 4; mt++) {
            int r = i0 + wm0 + mt * 16 + gid;
            unsigned w0 = adjb[(((size_t)(b * Nn + r)) << 5) + wq];
            unsigned w1 = adjb[(((size_t)(b * Nn + r + 8)) << 5) + wq];
#pragma unroll
            for (int nt = 0; nt < 4; nt++) {
                int bit = nt * 8 + 2 * tid4;
                sac[mt][nt][0] = (w0 >> bit) & 1       ? sac[mt][nt][0] * 0.0625f : -1e30f;
                sac[mt][nt][1] = (w0 >> (bit + 1)) & 1 ? sac[mt][nt][1] * 0.0625f : -1e30f;
                sac[mt][nt][2] = (w1 >> bit) & 1       ? sac[mt][nt][2] * 0.0625f : -1e30f;
                sac[mt][nt][3] = (w1 >> (bit + 1)) & 1 ? sac[mt][nt][3] * 0.0625f : -1e30f;
                tmax[mt * 2 + 0] = fmaxf(tmax[mt * 2 + 0],
                                         fmaxf(sac[mt][nt][0], sac[mt][nt][1]));
                tmax[mt * 2 + 1] = fmaxf(tmax[mt * 2 + 1],
                                         fmaxf(sac[mt][nt][2], sac[mt][nt][3]));
            }
        }
#pragma unroll
        for (int s = 0; s < 8; s++) {
            tmax[s] = fmaxf(tmax[s], __shfl_xor_sync(0xffffffffu, tmax[s], 1));
            tmax[s] = fmaxf(tmax[s], __shfl_xor_sync(0xffffffffu, tmax[s], 2));
        }
        if (tid4 == 0) {
#pragma unroll
            for (int mt = 0; mt < 4; mt++) {
                redm[(w & 3) * 128 + wm0 + mt * 16 + gid]     = tmax[mt * 2];
                redm[(w & 3) * 128 + wm0 + mt * 16 + gid + 8] = tmax[mt * 2 + 1];
            }
        }
        __syncthreads();

        float alp[8];
#pragma unroll
        for (int mt = 0; mt < 4; mt++)
#pragma unroll
            for (int q = 0; q < 2; q++) {
                int r = wm0 + mt * 16 + gid + q * 8;
                float tm = fmaxf(fmaxf(redm[r], redm[128 + r]),
                                 fmaxf(redm[256 + r], redm[384 + r]));
                int s = mt * 2 + q;
                float mn = fmaxf(m_st[s], fmaxf(tm, -1e4f));
                alp[s] = __expf(m_st[s] - mn);
                m_st[s] = mn;
            }

        // ---- exp, partial sums, store P bf16 [i][j] ----
        float psum[8] = {};
#pragma unroll
        for (int mt = 0; mt < 4; mt++) {
            int r = wm0 + mt * 16 + gid;
            int s0 = mt * 2, s1 = mt * 2 + 1;
#pragma unroll
            for (int nt = 0; nt < 4; nt++) {
                int c = wn0 + nt * 8 + 2 * tid4;
                float e0 = __expf(sac[mt][nt][0] - m_st[s0]);
                float e1 = __expf(sac[mt][nt][1] - m_st[s0]);
                float e2 = __expf(sac[mt][nt][2] - m_st[s1]);
                float e3 = __expf(sac[mt][nt][3] - m_st[s1]);
                psum[s0] += e0 + e1;
                psum[s1] += e2 + e3;
                *(unsigned*)(smc + FP_B + r * 272 + c * 2)       = packbf(e0, e1);
                *(unsigned*)(smc + FP_B + (r + 8) * 272 + c * 2) = packbf(e2, e3);
            }
        }
#pragma unroll
        for (int s = 0; s < 8; s++) {
            psum[s] += __shfl_xor_sync(0xffffffffu, psum[s], 1);
            psum[s] += __shfl_xor_sync(0xffffffffu, psum[s], 2);
        }
        if (tid4 == 0) {
#pragma unroll
            for (int mt = 0; mt < 4; mt++) {
                reds[(w & 3) * 128 + wm0 + mt * 16 + gid]     = psum[mt * 2];
                reds[(w & 3) * 128 + wm0 + mt * 16 + gid + 8] = psum[mt * 2 + 1];
            }
        }
        __syncthreads();

        // ---- update l, rescale O ----
#pragma unroll
        for (int mt = 0; mt < 4; mt++)
#pragma unroll
            for (int q = 0; q < 2; q++) {
                int r = wm0 + mt * 16 + gid + q * 8;
                int s = mt * 2 + q;
                float ps = reds[r] + reds[128 + r] + reds[256 + r] + reds[384 + r];
                l_st[s] = l_st[s] * alp[s] + ps;
            }
#pragma unroll
        for (int mt = 0; mt < 4; mt++)
#pragma unroll
            for (int nt = 0; nt < 2; nt++) {
                oac[mt][nt][0] *= alp[mt * 2];
                oac[mt][nt][1] *= alp[mt * 2];
                oac[mt][nt][2] *= alp[mt * 2 + 1];
                oac[mt][nt][3] *= alp[mt * 2 + 1];
            }

        // ---- O += P @ V (128x64, k=128) ----
#pragma unroll
        for (int ko = 0; ko < 128; ko += 16) {
            unsigned af[4][4], bfr[2][2];
            {
                unsigned r[4];
                unsigned addr = sbase + FV_B + (ko + vrow) * 144 + vcoff;
                ldsm4t(addr, r);
                bfr[0][0] = r[0]; bfr[0][1] = r[1];
                bfr[1][0] = r[2]; bfr[1][1] = r[3];
            }
#pragma unroll
            for (int mt = 0; mt < 4; mt++) {
                unsigned addr = sbase + FP_B + (wm0 + mt * 16 + arow) * 272
                              + ko * 2 + acoff;
                ldsm4(addr, af[mt]);
            }
#pragma unroll
            for (int mt = 0; mt < 4; mt++)
#pragma unroll
                for (int nt = 0; nt < 2; nt++)
                    BF16_MMA(oac[mt][nt], af[mt], bfr[nt]);
        }
    }

    // ---- epilogue: O/l + residual X ----
    float inv[8];
#pragma unroll
    for (int s = 0; s < 8; s++) inv[s] = 1.f / l_st[s];
#pragma unroll
    for (int mt = 0; mt < 4; mt++) {
        int r = i0 + wm0 + mt * 16 + gid;
#pragma unroll
        for (int nt = 0; nt < 2; nt++) {
            int c = wd0 + nt * 8 + 2 * tid4;
            size_t idx0 = (size_t)(b * Nn + r) * Hd + h * 64 + c;
            size_t idx1 = (size_t)(b * Nn + r + 8) * Hd + h * 64 + c;
            float2 x0 = *(const float2*)&X[idx0];
            float2 x1 = *(const float2*)&X[idx1];
            *(float2*)&O[idx0] = make_float2(oac[mt][nt][0] * inv[mt * 2] + x0.x,
                                             oac[mt][nt][1] * inv[mt * 2] + x0.y);
            *(float2*)&O[idx1] = make_float2(oac[mt][nt][2] * inv[mt * 2 + 1] + x1.x,
                                             oac[mt][nt][3] * inv[mt * 2 + 1] + x1.y);
        }
    }
}

// ---------------------------------------------------------------------------
// LayerNorm: one warp per row (256 floats, 8 per thread), shuffle reductions.
// grid = Mrows/8 blocks x 256 threads.
// ---------------------------------------------------------------------------
__global__ void ln_kernel(const float* __restrict__ A,
                          const float* __restrict__ Badd,
                          const float* __restrict__ gamma,
                          const float* __restrict__ beta,
                          float* __restrict__ out)
{
    int row  = (blockIdx.x * blockDim.x + threadIdx.x) >> 5;
    int lane = threadIdx.x & 31;
    size_t base = (size_t)row * Hd + lane * 8;

    float4 v0 = *(const float4*)&A[base];
    float4 v1 = *(const float4*)&A[base + 4];
    if (Badd) {
        float4 b0 = *(const float4*)&Badd[base];
        float4 b1 = *(const float4*)&Badd[base + 4];
        v0.x += b0.x; v0.y += b0.y; v0.z += b0.z; v0.w += b0.w;
        v1.x += b1.x; v1.y += b1.y; v1.z += b1.z; v1.w += b1.w;
    }

    float s = v0.x + v0.y + v0.z + v0.w + v1.x + v1.y + v1.z + v1.w;
#pragma unroll
    for (int off = 16; off > 0; off >>= 1)
        s += __shfl_xor_sync(0xffffffffu, s, off);
    float mean = s * (1.f / Hd);

    float d0x = v0.x - mean, d0y = v0.y - mean, d0z = v0.z - mean, d0w = v0.w - mean;
    float d1x = v1.x - mean, d1y = v1.y - mean, d1z = v1.z - mean, d1w = v1.w - mean;
    float q = d0x * d0x + d0y * d0y + d0z * d0z + d0w * d0w
            + d1x * d1x + d1y * d1y + d1z * d1z + d1w * d1w;
#pragma unroll
    for (int off = 16; off > 0; off >>= 1)
        q += __shfl_xor_sync(0xffffffffu, q, off);
    float rstd = rsqrtf(q * (1.f / Hd) + 1e-5f);

    int c = lane * 8;
    float4 g0 = *(const float4*)&gamma[c];
    float4 g1 = *(const float4*)&gamma[c + 4];
    float4 b0 = *(const float4*)&beta[c];
    float4 b1 = *(const float4*)&beta[c + 4];
    *(float4*)&out[base] = make_float4(d0x * rstd * g0.x + b0.x,
                                       d0y * rstd * g0.y + b0.y,
                                       d0z * rstd * g0.z + b0.z,
                                       d0w * rstd * g0.w + b0.w);
    *(float4*)&out[base + 4] = make_float4(d1x * rstd * g1.x + b1.x,
                                           d1y * rstd * g1.y + b1.y,
                                           d1z * rstd * g1.z + b1.z,
                                           d1w * rstd * g1.w + b1.w);
}

// ---------------------------------------------------------------------------
__global__ void fill_tail_kernel(float* __restrict__ out, int start, int total)
{
    int i = blockIdx.x * blockDim.x + threadIdx.x + start;
    if (i < total) out[i] = 1.0f;
}

// ---------------------------------------------------------------------------
extern "C" void kernel_launch(void* const* d_in, const int* in_sizes, int n_in,
                              void* d_out, int out_size)
{
    const int*   ents      = (const int*)  d_in[0];
    const int*   rels      = (const int*)  d_in[1];
    const int*   adjs      = (const int*)  d_in[2];
    const float* ent_table = (const float*)d_in[3];
    const float* rel_table = (const float*)d_in[4];
    const float* Wq        = (const float*)d_in[5];
    const float* Wk        = (const float*)d_in[6];
    const float* Wv        = (const float*)d_in[7];
    const float* l1w       = (const float*)d_in[8];
    const float* l1b       = (const float*)d_in[9];
    const float* l2w       = (const float*)d_in[10];
    const float* l2b       = (const float*)d_in[11];
    const float* ln_g      = (const float*)d_in[12];
    const float* ln_b      = (const float*)d_in[13];
    const float* alpha     = (const float*)d_in[14];
    float* out = (float*)d_out;

    float *x, *qkv, *o, *tb, *h1, *h2, *wqkv;
    unsigned* adjb;
    cudaGetSymbolAddress((void**)&x,    g_x);
    cudaGetSymbolAddress((void**)&qkv,  g_qkv);
    cudaGetSymbolAddress((void**)&o,    g_o);
    cudaGetSymbolAddress((void**)&tb,   g_t);
    cudaGetSymbolAddress((void**)&h1,   g_h1);
    cudaGetSymbolAddress((void**)&h2,   g_h2);
    cudaGetSymbolAddress((void**)&wqkv, g_wqkv);
    cudaGetSymbolAddress((void**)&adjb, g_adjb);

    cudaFuncSetAttribute(flash_attn, cudaFuncAttributeMaxDynamicSharedMemorySize,
                         FL_SMEM);

    embed_kernel<<<Bsz * Nn, 256>>>(ents, rels, ent_table, rel_table, x);
    adjpack_kernel<<<Bsz * Nn * 32 / 8, 256>>>(adjs, adjb);

    for (int j = 0; j < 2; j++) {
        const float* wq = Wq  + (size_t)j * Hd * Hd;
        const float* wk = Wk  + (size_t)j * Hd * Hd;
        const float* wv = Wv  + (size_t)j * Hd * Hd;
        const float* w1 = l1w + (size_t)j * Hd * 4 * Hd;
        const float* b1 = l1b + (size_t)j * 4 * Hd;
        const float* w2 = l2w + (size_t)j * 4 * Hd * Hd;
        const float* b2 = l2b + (size_t)j * Hd;
        const float* lg = ln_g + (size_t)j * Hd;
        const float* lb = ln_b + (size_t)j * Hd;
        const float* al = alpha + (size_t)j * 4 * Hd;

        packw_kernel<<<768, 256>>>(wq, wk, wv, wqkv);

        gemm_tc<<<dim3(6, 128), 256>>>(x, wqkv, qkv,
                                       Hd, Hd, 768, 768, nullptr, nullptr, 0);

        flash_attn<<<dim3(8, Bsz * 4), 256, FL_SMEM>>>(qkv, adjb, x, o);

        ln_kernel<<<Mrows / 8, 256>>>(o, nullptr, lg, lb, tb);

        gemm_tc<<<dim3(8, 128), 256>>>(tb, w1, h1,
                                       Hd, Hd, 4 * Hd, 4 * Hd, b1, al, 1);
        gemm_tc<<<dim3(2, 128), 256>>>(h1, w2, h2,
                                       4 * Hd, 4 * Hd, Hd, Hd, b2, nullptr, 2);

        float* dst = (j == 1) ? out : x;
        ln_kernel<<<Mrows / 8, 256>>>(h2, tb, lg, lb, dst);
    }

    int tail = out_size - XSZ;
    if (tail > 0)
        fill_tail_kernel<<<(tail + 255) / 256, 256>>>(out, XSZ, out_size);
}

// round 9
// speedup vs baseline: 1.6922x; 1.6922x over previous
#include <cuda_runtime.h>
#include <cuda_bf16.h>

// ---------------------------------------------------------------------------
// graph_encoder: B=16, N=1024, H=256, 4 heads (d=64), 2 layers.
// R8: R6 mma structure + bf16 activation/weight storage (no hot-loop cvt),
//     ktrans removed, warp-per-row LN.
// ---------------------------------------------------------------------------

#define Bsz   16
#define Nn    1024
#define Hd    256
#define Ee    767
#define Rr    256
#define ROOTI 46
#define Mrows (Bsz * Nn)
#define XSZ   (Mrows * Hd)
#define H1SZ  (Mrows * 4 * Hd)
#define QKVSZ (Mrows * 3 * Hd)

__device__ float          g_x  [XSZ];      // fp32 residual state
__device__ __nv_bfloat16  g_xb [XSZ];      // bf16 copy for GEMM A
__device__ __nv_bfloat16  g_qkvb[QKVSZ];   // [16384, 768] bf16 (q|k|v)
__device__ float          g_o  [XSZ];
__device__ float          g_t  [XSZ];      // fp32 LN output (residual)
__device__ __nv_bfloat16  g_tb [XSZ];      // bf16 LN output
__device__ float          g_h2 [XSZ];
__device__ __nv_bfloat16  g_h1b[H1SZ];
__device__ __nv_bfloat16  g_wqkvb[2 * Hd * 3 * Hd];
__device__ __nv_bfloat16  g_w1b  [2 * Hd * 4 * Hd];
__device__ __nv_bfloat16  g_w2b  [2 * 4 * Hd * Hd];
__device__ unsigned       g_adjb[Bsz * Nn * 32];

// ---------------------------------------------------------------------------
__device__ __forceinline__ unsigned packbf(float lo, float hi)
{
    unsigned u;
    asm("cvt.rn.bf16x2.f32 %0, %1, %2;" : "=r"(u) : "f"(hi), "f"(lo));
    return u;
}
__device__ __forceinline__ unsigned prmt(unsigned a, unsigned b, unsigned s)
{
    unsigned r;
    asm("prmt.b32 %0, %1, %2, %3;" : "=r"(r) : "r"(a), "r"(b), "r"(s));
    return r;
}

#define BF16_MMA(d, a, b)                                                     \
    asm volatile(                                                             \
        "mma.sync.aligned.m16n8k16.row.col.f32.bf16.bf16.f32 "                \
        "{%0,%1,%2,%3},{%4,%5,%6,%7},{%8,%9},{%0,%1,%2,%3};"                  \
        : "+f"((d)[0]), "+f"((d)[1]), "+f"((d)[2]), "+f"((d)[3])              \
        : "r"((a)[0]), "r"((a)[1]), "r"((a)[2]), "r"((a)[3]),                 \
          "r"((b)[0]), "r"((b)[1]))

// ---------------------------------------------------------------------------
__global__ void embed_kernel(const int* __restrict__ ents,
                             const int* __restrict__ rels,
                             const float* __restrict__ ent_table,
                             const float* __restrict__ rel_table,
                             float* __restrict__ x,
                             __nv_bfloat16* __restrict__ xb)
{
    int bn = blockIdx.x;
    int b  = bn >> 10;
    int n  = bn & 1023;
    const float* src;
    if (n < Ee)            src = ent_table + (size_t)ents[b * Ee + n] * Hd;
    else if (n < Ee + Rr)  src = rel_table + (size_t)rels[b * Rr + (n - Ee)] * Hd;
    else                   src = rel_table + (size_t)ROOTI * Hd;
    float v = src[threadIdx.x];
    size_t idx = (size_t)bn * Hd + threadIdx.x;
    x[idx]  = v;
    xb[idx] = __float2bfloat16(v);
}

// ---------------------------------------------------------------------------
__global__ void packqkv_kernel(const float* __restrict__ wq,
                               const float* __restrict__ wk,
                               const float* __restrict__ wv,
                               __nv_bfloat16* __restrict__ out)
{
    int j = blockIdx.y;
    int i = blockIdx.x * 256 + threadIdx.x;   // 0..196607
    int k = i / 768, c = i - k * 768;
    const float* base;
    int cc;
    if (c < 256)      { base = wq; cc = c; }
    else if (c < 512) { base = wk; cc = c - 256; }
    else              { base = wv; cc = c - 512; }
    out[(size_t)j * 196608 + i] =
        __float2bfloat16(base[(size_t)j * 65536 + k * 256 + cc]);
}

__global__ void cvt_bf_kernel(const float* __restrict__ in,
                              __nv_bfloat16* __restrict__ out)
{
    int i = blockIdx.x * 256 + threadIdx.x;
    out[i] = __float2bfloat16(in[i]);
}

// ---------------------------------------------------------------------------
__global__ void adjpack_kernel(const int* __restrict__ adj,
                               unsigned* __restrict__ adjb)
{
    int gw   = blockIdx.x * 8 + (threadIdx.x >> 5);
    int lane = threadIdx.x & 31;
    int row  = gw >> 5;
    int wrd  = gw & 31;
    int v = adj[((size_t)row << 10) + wrd * 32 + lane];
    unsigned m = __ballot_sync(0xffffffffu, v != 0);
    if (lane == 0) adjb[gw] = m;
}

// ---------------------------------------------------------------------------
// bf16 GEMM (R6 structure): 128x128 block, 8 warps (2x4), warp 64x32, k16.
// A bf16 [m][k], W bf16 [k][n]. Output fp32 (Cf) or bf16 (Cb).
// mode: 0 plain, 1 bias+PReLU, 2 bias.
// ---------------------------------------------------------------------------
__global__ void __launch_bounds__(256, 2)
gemm_tc(const __nv_bfloat16* __restrict__ A,
        const __nv_bfloat16* __restrict__ W,
        float* __restrict__ Cf,
        __nv_bfloat16* __restrict__ Cb,
        int K, int lda, int ldb, int ldc,
        const float* __restrict__ bias,
        const float* __restrict__ alpha,
        int mode)
{
    __shared__ unsigned As[2][8][132];   // word kw = k pair, indexed [kw][m]
    __shared__ unsigned Bs[2][8][132];   // word kw = k pair, indexed [kw][n]

    int t    = threadIdx.x;
    int w    = t >> 5, lane = t & 31;
    int gid  = lane >> 2, tid4 = lane & 3;
    int wm0  = (w >> 2) * 64;
    int wn0  = (w & 3) * 32;
    int row0 = blockIdx.y << 7;
    int col0 = blockIdx.x << 7;

    int am  = t >> 1;            // A row
    int aw0 = (t & 1) * 4;       // A word offset (k elems = aw0*2)
    int bkw = t >> 5;            // B word row 0..7
    int bn4 = (t & 31) * 4;      // 4 n per thread

    const __nv_bfloat16* Ap  = A + (size_t)(row0 + am) * lda + aw0 * 2;
    const __nv_bfloat16* Bp0 = W + (size_t)(bkw * 2) * ldb + col0 + bn4;
    const __nv_bfloat16* Bp1 = Bp0 + ldb;

    {
        uint4 a = *(const uint4*)Ap;
        As[0][aw0 + 0][am] = a.x; As[0][aw0 + 1][am] = a.y;
        As[0][aw0 + 2][am] = a.z; As[0][aw0 + 3][am] = a.w;
        uint2 u = *(const uint2*)Bp0;
        uint2 v = *(const uint2*)Bp1;
        Bs[0][bkw][bn4 + 0] = prmt(u.x, v.x, 0x5410);
        Bs[0][bkw][bn4 + 1] = prmt(u.x, v.x, 0x7632);
        Bs[0][bkw][bn4 + 2] = prmt(u.y, v.y, 0x5410);
        Bs[0][bkw][bn4 + 3] = prmt(u.y, v.y, 0x7632);
    }
    __syncthreads();

    float acc[4][4][4] = {};
    int buf = 0;

    for (int k0 = 16; k0 <= K; k0 += 16) {
        uint4 na; uint2 nu, nv;
        if (k0 < K) {
            na = *(const uint4*)(Ap + k0);
            nu = *(const uint2*)(Bp0 + (size_t)k0 * ldb);
            nv = *(const uint2*)(Bp1 + (size_t)k0 * ldb);
        }
        {
            unsigned af[4][4], bfr[4][2];
#pragma unroll
            for (int nt = 0; nt < 4; nt++) {
                bfr[nt][0] = Bs[buf][tid4][wn0 + nt * 8 + gid];
                bfr[nt][1] = Bs[buf][tid4 + 4][wn0 + nt * 8 + gid];
            }
#pragma unroll
            for (int mt = 0; mt < 4; mt++) {
                af[mt][0] = As[buf][tid4][wm0 + mt * 16 + gid];
                af[mt][1] = As[buf][tid4][wm0 + mt * 16 + gid + 8];
                af[mt][2] = As[buf][tid4 + 4][wm0 + mt * 16 + gid];
                af[mt][3] = As[buf][tid4 + 4][wm0 + mt * 16 + gid + 8];
            }
#pragma unroll
            for (int mt = 0; mt < 4; mt++)
#pragma unroll
                for (int nt = 0; nt < 4; nt++)
                    BF16_MMA(acc[mt][nt], af[mt], bfr[nt]);
        }
        if (k0 < K) {
            buf ^= 1;
            As[buf][aw0 + 0][am] = na.x; As[buf][aw0 + 1][am] = na.y;
            As[buf][aw0 + 2][am] = na.z; As[buf][aw0 + 3][am] = na.w;
            Bs[buf][bkw][bn4 + 0] = prmt(nu.x, nv.x, 0x5410);
            Bs[buf][bkw][bn4 + 1] = prmt(nu.x, nv.x, 0x7632);
            Bs[buf][bkw][bn4 + 2] = prmt(nu.y, nv.y, 0x5410);
            Bs[buf][bkw][bn4 + 3] = prmt(nu.y, nv.y, 0x7632);
            __syncthreads();
        }
    }

#pragma unroll
    for (int mt = 0; mt < 4; mt++) {
        int r0 = row0 + wm0 + mt * 16 + gid;
#pragma unroll
        for (int nt = 0; nt < 4; nt++) {
            int c = col0 + wn0 + nt * 8 + 2 * tid4;
            float v0 = acc[mt][nt][0], v1 = acc[mt][nt][1];
            float v2 = acc[mt][nt][2], v3 = acc[mt][nt][3];
            if (mode != 0) {
                float b0v = bias[c], b1v = bias[c + 1];
                v0 += b0v; v1 += b1v; v2 += b0v; v3 += b1v;
            }
            if (mode == 1) {
                float a0v = alpha[c], a1v = alpha[c + 1];
                v0 = v0 >= 0.f ? v0 : a0v * v0;
                v1 = v1 >= 0.f ? v1 : a1v * v1;
                v2 = v2 >= 0.f ? v2 : a0v * v2;
                v3 = v3 >= 0.f ? v3 : a1v * v3;
            }
            if (Cf) {
                *(float2*)&Cf[(size_t)r0 * ldc + c]       = make_float2(v0, v1);
                *(float2*)&Cf[(size_t)(r0 + 8) * ldc + c] = make_float2(v2, v3);
            } else {
                *(unsigned*)&Cb[(size_t)r0 * ldc + c]       = packbf(v0, v1);
                *(unsigned*)&Cb[(size_t)(r0 + 8) * ldc + c] = packbf(v2, v3);
            }
        }
    }
}

// ---------------------------------------------------------------------------
// Fused flash attention (R6 layouts), K/V straight from bf16 qkv (no ktrans).
// Smem words: Qs[32][136] Ks[32][136] Vs[64][72] Ps[64][136] red[1024]
// ---------------------------------------------------------------------------
#define FL_QS   0
#define FL_KS   (32 * 136)
#define FL_VS   (FL_KS + 32 * 136)
#define FL_PS   (FL_VS + 64 * 72)
#define FL_RED  (FL_PS + 64 * 136)
#define FL_SMEM ((FL_RED + 2 * 4 * 128) * 4)

__global__ void __launch_bounds__(256, 2)
flash_attn(const __nv_bfloat16* __restrict__ qkv,
           const unsigned* __restrict__ adjb,
           const float* __restrict__ X,
           float* __restrict__ O)
{
    extern __shared__ unsigned sm[];
    unsigned* Qs = sm + FL_QS;
    unsigned* Ks = sm + FL_KS;
    unsigned* Vs = sm + FL_VS;
    unsigned* Ps = sm + FL_PS;
    float* redm = (float*)(sm + FL_RED);
    float* reds = redm + 4 * 128;

    int t = threadIdx.x;
    int w = t >> 5, lane = t & 31;
    int gid = lane >> 2, tid4 = lane & 3;
    int wm0 = (w >> 2) * 64;
    int wn0 = (w & 3) * 32;
    int wd0 = (w & 3) * 16;
    int z = blockIdx.y;
    int b = z >> 2, h = z & 3;
    int i0 = blockIdx.x << 7;

    // ---- Q tile: Qs[dw][i], words are (d,d+1) pairs -> direct row load ----
    {
        int i   = t >> 1;
        int dw0 = (t & 1) * 16;
        const __nv_bfloat16* src = qkv + (size_t)(b * Nn + i0 + i) * 768
                                 + h * 64 + dw0 * 2;
        uint4 q0 = *(const uint4*)src;
        uint4 q1 = *(const uint4*)(src + 8);
        uint4 q2 = *(const uint4*)(src + 16);
        uint4 q3 = *(const uint4*)(src + 24);
        unsigned qs[16] = {q0.x,q0.y,q0.z,q0.w, q1.x,q1.y,q1.z,q1.w,
                           q2.x,q2.y,q2.z,q2.w, q3.x,q3.y,q3.z,q3.w};
#pragma unroll
        for (int c = 0; c < 16; c++)
            Qs[(dw0 + c) * 136 + i] = qs[c];
    }

    float m_st[8], l_st[8];
    float oac[4][2][4] = {};
#pragma unroll
    for (int s = 0; s < 8; s++) { m_st[s] = -1e4f; l_st[s] = 0.f; }

    for (int jt = 0; jt < 8; jt++) {
        int j0 = jt << 7;
        __syncthreads();

        // ---- K tile: Ks[dw][j] (d-pair words, direct row load) ----
        {
            int jj  = t >> 1;
            int dw0 = (t & 1) * 16;
            const __nv_bfloat16* src = qkv + (size_t)(b * Nn + j0 + jj) * 768
                                     + 256 + h * 64 + dw0 * 2;
            uint4 k0 = *(const uint4*)src;
            uint4 k1 = *(const uint4*)(src + 8);
            uint4 k2 = *(const uint4*)(src + 16);
            uint4 k3 = *(const uint4*)(src + 24);
            unsigned ks[16] = {k0.x,k0.y,k0.z,k0.w, k1.x,k1.y,k1.z,k1.w,
                               k2.x,k2.y,k2.z,k2.w, k3.x,k3.y,k3.z,k3.w};
#pragma unroll
            for (int c = 0; c < 16; c++)
                Ks[(dw0 + c) * 136 + jj] = ks[c];
        }
        // ---- V tile: Vs[jw][d] (j-pair words via prmt) ----
        {
            int jw = t >> 2;
            int d0 = (t & 3) * 16;
            const __nv_bfloat16* r0 = qkv + (size_t)(b * Nn + j0 + 2 * jw) * 768
                                    + 512 + h * 64 + d0;
            const __nv_bfloat16* r1 = r0 + 768;
            uint4 ua = *(const uint4*)r0;
            uint4 ub = *(const uint4*)(r0 + 8);
            uint4 va = *(const uint4*)r1;
            uint4 vb = *(const uint4*)(r1 + 8);
            unsigned* dst = &Vs[jw * 72 + d0];
            *(uint4*)(dst)      = make_uint4(prmt(ua.x, va.x, 0x5410),
                                             prmt(ua.x, va.x, 0x7632),
                                             prmt(ua.y, va.y, 0x5410),
                                             prmt(ua.y, va.y, 0x7632));
            *(uint4*)(dst + 4)  = make_uint4(prmt(ua.z, va.z, 0x5410),
                                             prmt(ua.z, va.z, 0x7632),
                                             prmt(ua.w, va.w, 0x5410),
                                             prmt(ua.w, va.w, 0x7632));
            *(uint4*)(dst + 8)  = make_uint4(prmt(ub.x, vb.x, 0x5410),
                                             prmt(ub.x, vb.x, 0x7632),
                                             prmt(ub.y, vb.y, 0x5410),
                                             prmt(ub.y, vb.y, 0x7632));
            *(uint4*)(dst + 12) = make_uint4(prmt(ub.z, vb.z, 0x5410),
                                             prmt(ub.z, vb.z, 0x7632),
                                             prmt(ub.w, vb.w, 0x5410),
                                             prmt(ub.w, vb.w, 0x7632));
        }
        __syncthreads();

        // ---- S = Q @ K^T (128x128, d=64 -> 32 words) ----
        float sac[4][4][4] = {};
#pragma unroll
        for (int ko = 0; ko < 32; ko += 8) {
            unsigned af[4][4], bfr[4][2];
#pragma unroll
            for (int nt = 0; nt < 4; nt++) {
                bfr[nt][0] = Ks[(ko + tid4) * 136 + wn0 + nt * 8 + gid];
                bfr[nt][1] = Ks[(ko + tid4 + 4) * 136 + wn0 + nt * 8 + gid];
            }
#pragma unroll
            for (int mt = 0; mt < 4; mt++) {
                af[mt][0] = Qs[(ko + tid4) * 136 + wm0 + mt * 16 + gid];
                af[mt][1] = Qs[(ko + tid4) * 136 + wm0 + mt * 16 + gid + 8];
                af[mt][2] = Qs[(ko + tid4 + 4) * 136 + wm0 + mt * 16 + gid];
                af[mt][3] = Qs[(ko + tid4 + 4) * 136 + wm0 + mt * 16 + gid + 8];
            }
#pragma unroll
            for (int mt = 0; mt < 4; mt++)
#pragma unroll
                for (int nt = 0; nt < 4; nt++)
                    BF16_MMA(sac[mt][nt], af[mt], bfr[nt]);
        }

        // ---- mask (bitpacked) + scale, per-row tile max ----
        int wq = (j0 + wn0) >> 5;
        float tmax[8];
#pragma unroll
        for (int s = 0; s < 8; s++) tmax[s] = -1e30f;
#pragma unroll
        for (int mt = 0; mt < 4; mt++) {
            int r = i0 + wm0 + mt * 16 + gid;
            unsigned w0 = adjb[(((size_t)(b * Nn + r)) << 5) + wq];
            unsigned w1 = adjb[(((size_t)(b * Nn + r + 8)) << 5) + wq];
#pragma unroll
            for (int nt = 0; nt < 4; nt++) {
                int bit = nt * 8 + 2 * tid4;
                sac[mt][nt][0] = (w0 >> bit) & 1       ? sac[mt][nt][0] * 0.0625f : -1e30f;
                sac[mt][nt][1] = (w0 >> (bit + 1)) & 1 ? sac[mt][nt][1] * 0.0625f : -1e30f;
                sac[mt][nt][2] = (w1 >> bit) & 1       ? sac[mt][nt][2] * 0.0625f : -1e30f;
                sac[mt][nt][3] = (w1 >> (bit + 1)) & 1 ? sac[mt][nt][3] * 0.0625f : -1e30f;
                tmax[mt * 2 + 0] = fmaxf(tmax[mt * 2 + 0],
                                         fmaxf(sac[mt][nt][0], sac[mt][nt][1]));
                tmax[mt * 2 + 1] = fmaxf(tmax[mt * 2 + 1],
                                         fmaxf(sac[mt][nt][2], sac[mt][nt][3]));
            }
        }
#pragma unroll
        for (int s = 0; s < 8; s++) {
            tmax[s] = fmaxf(tmax[s], __shfl_xor_sync(0xffffffffu, tmax[s], 1));
            tmax[s] = fmaxf(tmax[s], __shfl_xor_sync(0xffffffffu, tmax[s], 2));
        }
        if (tid4 == 0) {
#pragma unroll
            for (int mt = 0; mt < 4; mt++) {
                redm[(w & 3) * 128 + wm0 + mt * 16 + gid]     = tmax[mt * 2];
                redm[(w & 3) * 128 + wm0 + mt * 16 + gid + 8] = tmax[mt * 2 + 1];
            }
        }
        __syncthreads();

        float alp[8];
#pragma unroll
        for (int mt = 0; mt < 4; mt++)
#pragma unroll
            for (int q = 0; q < 2; q++) {
                int r = wm0 + mt * 16 + gid + q * 8;
                float tm = fmaxf(fmaxf(redm[r], redm[128 + r]),
                                 fmaxf(redm[256 + r], redm[384 + r]));
                int s = mt * 2 + q;
                float mn = fmaxf(m_st[s], fmaxf(tm, -1e4f));
                alp[s] = __expf(m_st[s] - mn);
                m_st[s] = mn;
            }

        // ---- exp, partial sums, store P (bf16 pairs along j) ----
        float psum[8] = {};
#pragma unroll
        for (int mt = 0; mt < 4; mt++) {
            int r = wm0 + mt * 16 + gid;
            int s0 = mt * 2, s1 = mt * 2 + 1;
#pragma unroll
            for (int nt = 0; nt < 4; nt++) {
                int cw = (wn0 >> 1) + nt * 4 + tid4;
                float e0 = __expf(sac[mt][nt][0] - m_st[s0]);
                float e1 = __expf(sac[mt][nt][1] - m_st[s0]);
                float e2 = __expf(sac[mt][nt][2] - m_st[s1]);
                float e3 = __expf(sac[mt][nt][3] - m_st[s1]);
                psum[s0] += e0 + e1;
                psum[s1] += e2 + e3;
                Ps[cw * 136 + r]     = packbf(e0, e1);
                Ps[cw * 136 + r + 8] = packbf(e2, e3);
            }
        }
#pragma unroll
        for (int s = 0; s < 8; s++) {
            psum[s] += __shfl_xor_sync(0xffffffffu, psum[s], 1);
            psum[s] += __shfl_xor_sync(0xffffffffu, psum[s], 2);
        }
        if (tid4 == 0) {
#pragma unroll
            for (int mt = 0; mt < 4; mt++) {
                reds[(w & 3) * 128 + wm0 + mt * 16 + gid]     = psum[mt * 2];
                reds[(w & 3) * 128 + wm0 + mt * 16 + gid + 8] = psum[mt * 2 + 1];
            }
        }
        __syncthreads();

        // ---- update l, rescale O ----
#pragma unroll
        for (int mt = 0; mt < 4; mt++)
#pragma unroll
            for (int q = 0; q < 2; q++) {
                int r = wm0 + mt * 16 + gid + q * 8;
                int s = mt * 2 + q;
                float ps = reds[r] + reds[128 + r] + reds[256 + r] + reds[384 + r];
                l_st[s] = l_st[s] * alp[s] + ps;
            }
#pragma unroll
        for (int mt = 0; mt < 4; mt++)
#pragma unroll
            for (int nt = 0; nt < 2; nt++) {
                oac[mt][nt][0] *= alp[mt * 2];
                oac[mt][nt][1] *= alp[mt * 2];
                oac[mt][nt][2] *= alp[mt * 2 + 1];
                oac[mt][nt][3] *= alp[mt * 2 + 1];
            }

        // ---- O += P @ V (128x64, k=128 -> 64 words) ----
#pragma unroll
        for (int ko = 0; ko < 64; ko += 8) {
            unsigned af[4][4], bfr[2][2];
#pragma unroll
            for (int nt = 0; nt < 2; nt++) {
                bfr[nt][0] = Vs[(ko + tid4) * 72 + wd0 + nt * 8 + gid];
                bfr[nt][1] = Vs[(ko + tid4 + 4) * 72 + wd0 + nt * 8 + gid];
            }
#pragma unroll
            for (int mt = 0; mt < 4; mt++) {
                af[mt][0] = Ps[(ko + tid4) * 136 + wm0 + mt * 16 + gid];
                af[mt][1] = Ps[(ko + tid4) * 136 + wm0 + mt * 16 + gid + 8];
                af[mt][2] = Ps[(ko + tid4 + 4) * 136 + wm0 + mt * 16 + gid];
                af[mt][3] = Ps[(ko + tid4 + 4) * 136 + wm0 + mt * 16 + gid + 8];
            }
#pragma unroll
            for (int mt = 0; mt < 4; mt++)
#pragma unroll
                for (int nt = 0; nt < 2; nt++)
                    BF16_MMA(oac[mt][nt], af[mt], bfr[nt]);
        }
    }

    // ---- epilogue: O/l + residual X ----
    float inv[8];
#pragma unroll
    for (int s = 0; s < 8; s++) inv[s] = 1.f / l_st[s];
#pragma unroll
    for (int mt = 0; mt < 4; mt++) {
        int r = i0 + wm0 + mt * 16 + gid;
#pragma unroll
        for (int nt = 0; nt < 2; nt++) {
            int c = wd0 + nt * 8 + 2 * tid4;
            size_t idx0 = (size_t)(b * Nn + r) * Hd + h * 64 + c;
            size_t idx1 = (size_t)(b * Nn + r + 8) * Hd + h * 64 + c;
            float2 x0 = *(const float2*)&X[idx0];
            float2 x1 = *(const float2*)&X[idx1];
            *(float2*)&O[idx0] = make_float2(oac[mt][nt][0] * inv[mt * 2] + x0.x,
                                             oac[mt][nt][1] * inv[mt * 2] + x0.y);
            *(float2*)&O[idx1] = make_float2(oac[mt][nt][2] * inv[mt * 2 + 1] + x1.x,
                                             oac[mt][nt][3] * inv[mt * 2 + 1] + x1.y);
        }
    }
}

// ---------------------------------------------------------------------------
// LayerNorm: one warp per row, shuffle reductions. Optional bf16 second output.
// ---------------------------------------------------------------------------
__global__ void ln_kernel(const float* __restrict__ A,
                          const float* __restrict__ Badd,
                          const float* __restrict__ gamma,
                          const float* __restrict__ beta,
                          float* __restrict__ out,
                          __nv_bfloat16* __restrict__ outb)
{
    int row  = (blockIdx.x * blockDim.x + threadIdx.x) >> 5;
    int lane = threadIdx.x & 31;
    size_t base = (size_t)row * Hd + lane * 8;

    float4 v0 = *(const float4*)&A[base];
    float4 v1 = *(const float4*)&A[base + 4];
    if (Badd) {
        float4 b0 = *(const float4*)&Badd[base];
        float4 b1 = *(const float4*)&Badd[base + 4];
        v0.x += b0.x; v0.y += b0.y; v0.z += b0.z; v0.w += b0.w;
        v1.x += b1.x; v1.y += b1.y; v1.z += b1.z; v1.w += b1.w;
    }

    float s = v0.x + v0.y + v0.z + v0.w + v1.x + v1.y + v1.z + v1.w;
#pragma unroll
    for (int off = 16; off > 0; off >>= 1)
        s += __shfl_xor_sync(0xffffffffu, s, off);
    float mean = s * (1.f / Hd);

    float d0x = v0.x - mean, d0y = v0.y - mean, d0z = v0.z - mean, d0w = v0.w - mean;
    float d1x = v1.x - mean, d1y = v1.y - mean, d1z = v1.z - mean, d1w = v1.w - mean;
    float q = d0x * d0x + d0y * d0y + d0z * d0z + d0w * d0w
            + d1x * d1x + d1y * d1y + d1z * d1z + d1w * d1w;
#pragma unroll
    for (int off = 16; off > 0; off >>= 1)
        q += __shfl_xor_sync(0xffffffffu, q, off);
    float rstd = rsqrtf(q * (1.f / Hd) + 1e-5f);

    int c = lane * 8;
    float4 g0 = *(const float4*)&gamma[c];
    float4 g1 = *(const float4*)&gamma[c + 4];
    float4 b0 = *(const float4*)&beta[c];
    float4 b1 = *(const float4*)&beta[c + 4];
    float o0 = d0x * rstd * g0.x + b0.x;
    float o1 = d0y * rstd * g0.y + b0.y;
    float o2 = d0z * rstd * g0.z + b0.z;
    float o3 = d0w * rstd * g0.w + b0.w;
    float o4 = d1x * rstd * g1.x + b1.x;
    float o5 = d1y * rstd * g1.y + b1.y;
    float o6 = d1z * rstd * g1.z + b1.z;
    float o7 = d1w * rstd * g1.w + b1.w;
    *(float4*)&out[base]     = make_float4(o0, o1, o2, o3);
    *(float4*)&out[base + 4] = make_float4(o4, o5, o6, o7);
    if (outb) {
        *(uint4*)&outb[base] = make_uint4(packbf(o0, o1), packbf(o2, o3),
                                          packbf(o4, o5), packbf(o6, o7));
    }
}

// ---------------------------------------------------------------------------
__global__ void fill_tail_kernel(float* __restrict__ out, int start, int total)
{
    int i = blockIdx.x * blockDim.x + threadIdx.x + start;
    if (i < total) out[i] = 1.0f;
}

// ---------------------------------------------------------------------------
extern "C" void kernel_launch(void* const* d_in, const int* in_sizes, int n_in,
                              void* d_out, int out_size)
{
    const int*   ents      = (const int*)  d_in[0];
    const int*   rels      = (const int*)  d_in[1];
    const int*   adjs      = (const int*)  d_in[2];
    const float* ent_table = (const float*)d_in[3];
    const float* rel_table = (const float*)d_in[4];
    const float* Wq        = (const float*)d_in[5];
    const float* Wk        = (const float*)d_in[6];
    const float* Wv        = (const float*)d_in[7];
    const float* l1w       = (const float*)d_in[8];
    const float* l1b       = (const float*)d_in[9];
    const float* l2w       = (const float*)d_in[10];
    const float* l2b       = (const float*)d_in[11];
    const float* ln_g      = (const float*)d_in[12];
    const float* ln_b      = (const float*)d_in[13];
    const float* alpha     = (const float*)d_in[14];
    float* out = (float*)d_out;

    float *x, *o, *tb, *h2;
    __nv_bfloat16 *xb, *qkvb, *tbb, *h1b, *wqkvb, *w1b, *w2b;
    unsigned* adjb;
    cudaGetSymbolAddress((void**)&x,     g_x);
    cudaGetSymbolAddress((void**)&xb,    g_xb);
    cudaGetSymbolAddress((void**)&qkvb,  g_qkvb);
    cudaGetSymbolAddress((void**)&o,     g_o);
    cudaGetSymbolAddress((void**)&tb,    g_t);
    cudaGetSymbolAddress((void**)&tbb,   g_tb);
    cudaGetSymbolAddress((void**)&h2,    g_h2);
    cudaGetSymbolAddress((void**)&h1b,   g_h1b);
    cudaGetSymbolAddress((void**)&wqkvb, g_wqkvb);
    cudaGetSymbolAddress((void**)&w1b,   g_w1b);
    cudaGetSymbolAddress((void**)&w2b,   g_w2b);
    cudaGetSymbolAddress((void**)&adjb,  g_adjb);

    cudaFuncSetAttribute(flash_attn, cudaFuncAttributeMaxDynamicSharedMemorySize,
                         FL_SMEM);

    embed_kernel<<<Bsz * Nn, 256>>>(ents, rels, ent_table, rel_table, x, xb);
    adjpack_kernel<<<Bsz * Nn * 32 / 8, 256>>>(adjs, adjb);
    packqkv_kernel<<<dim3(768, 2), 256>>>(Wq, Wk, Wv, wqkvb);
    cvt_bf_kernel<<<2 * Hd * 4 * Hd / 256, 256>>>(l1w, w1b);
    cvt_bf_kernel<<<2 * 4 * Hd * Hd / 256, 256>>>(l2w, w2b);

    for (int j = 0; j < 2; j++) {
        const __nv_bfloat16* wqkv = wqkvb + (size_t)j * Hd * 3 * Hd;
        const __nv_bfloat16* w1   = w1b   + (size_t)j * Hd * 4 * Hd;
        const __nv_bfloat16* w2   = w2b   + (size_t)j * 4 * Hd * Hd;
        const float* b1 = l1b + (size_t)j * 4 * Hd;
        const float* b2 = l2b + (size_t)j * Hd;
        const float* lg = ln_g + (size_t)j * Hd;
        const float* lb = ln_b + (size_t)j * Hd;
        const float* al = alpha + (size_t)j * 4 * Hd;

        // QKV: [16384,256]bf16 @ [256,768]bf16 -> bf16
        gemm_tc<<<dim3(6, 128), 256>>>(xb, wqkv, nullptr, qkvb,
                                       Hd, Hd, 768, 768, nullptr, nullptr, 0);

        flash_attn<<<dim3(8, Bsz * 4), 256, FL_SMEM>>>(qkvb, adjb, x, o);

        ln_kernel<<<Mrows / 8, 256>>>(o, nullptr, lg, lb, tb, tbb);

        // MLP1: bf16 in/out, bias+PReLU
        gemm_tc<<<dim3(8, 128), 256>>>(tbb, w1, nullptr, h1b,
                                       Hd, Hd, 4 * Hd, 4 * Hd, b1, al, 1);
        // MLP2: bf16 in, fp32 out, bias
        gemm_tc<<<dim3(2, 128), 256>>>(h1b, w2, h2, nullptr,
                                       4 * Hd, 4 * Hd, Hd, Hd, b2, nullptr, 2);

        if (j == 0)
            ln_kernel<<<Mrows / 8, 256>>>(h2, tb, lg, lb, x, xb);
        else
            ln_kernel<<<Mrows / 8, 256>>>(h2, tb, lg, lb, out, nullptr);
    }

    int tail = out_size - XSZ;
    if (tail > 0)
        fill_tail_kernel<<<(tail + 255) / 256, 256>>>(out, XSZ, out_size);
}

// round 10
// speedup vs baseline: 1.8881x; 1.1158x over previous
#include <cuda_runtime.h>
#include <cuda_bf16.h>

// ---------------------------------------------------------------------------
// graph_encoder: B=16, N=1024, H=256, 4 heads (d=64), 2 layers.
// R9: conflict-free smem layouts + cp.async tile fills (gemm A, flash Q/K).
// ---------------------------------------------------------------------------

#define Bsz   16
#define Nn    1024
#define Hd    256
#define Ee    767
#define Rr    256
#define ROOTI 46
#define Mrows (Bsz * Nn)
#define XSZ   (Mrows * Hd)
#define H1SZ  (Mrows * 4 * Hd)
#define QKVSZ (Mrows * 3 * Hd)

__device__ float          g_x  [XSZ];
__device__ __nv_bfloat16  g_xb [XSZ];
__device__ __nv_bfloat16  g_qkvb[QKVSZ];
__device__ float          g_o  [XSZ];
__device__ float          g_t  [XSZ];
__device__ __nv_bfloat16  g_tb [XSZ];
__device__ float          g_h2 [XSZ];
__device__ __nv_bfloat16  g_h1b[H1SZ];
__device__ __nv_bfloat16  g_wqkvb[2 * Hd * 3 * Hd];
__device__ __nv_bfloat16  g_w1b  [2 * Hd * 4 * Hd];
__device__ __nv_bfloat16  g_w2b  [2 * 4 * Hd * Hd];
__device__ unsigned       g_adjb[Bsz * Nn * 32];

// ---------------------------------------------------------------------------
__device__ __forceinline__ unsigned packbf(float lo, float hi)
{
    unsigned u;
    asm("cvt.rn.bf16x2.f32 %0, %1, %2;" : "=r"(u) : "f"(hi), "f"(lo));
    return u;
}
__device__ __forceinline__ unsigned prmt(unsigned a, unsigned b, unsigned s)
{
    unsigned r;
    asm("prmt.b32 %0, %1, %2, %3;" : "=r"(r) : "r"(a), "r"(b), "r"(s));
    return r;
}
__device__ __forceinline__ void cpasync16(unsigned dst, const void* src)
{
    asm volatile("cp.async.cg.shared.global [%0], [%1], 16;\n"
                 :: "r"(dst), "l"(src));
}
#define CP_COMMIT asm volatile("cp.async.commit_group;\n" ::: "memory")
#define CP_WAIT0  asm volatile("cp.async.wait_group 0;\n" ::: "memory")

#define BF16_MMA(d, a, b)                                                     \
    asm volatile(                                                             \
        "mma.sync.aligned.m16n8k16.row.col.f32.bf16.bf16.f32 "                \
        "{%0,%1,%2,%3},{%4,%5,%6,%7},{%8,%9},{%0,%1,%2,%3};"                  \
        : "+f"((d)[0]), "+f"((d)[1]), "+f"((d)[2]), "+f"((d)[3])              \
        : "r"((a)[0]), "r"((a)[1]), "r"((a)[2]), "r"((a)[3]),                 \
          "r"((b)[0]), "r"((b)[1]))

// ---------------------------------------------------------------------------
__global__ void embed_kernel(const int* __restrict__ ents,
                             const int* __restrict__ rels,
                             const float* __restrict__ ent_table,
                             const float* __restrict__ rel_table,
                             float* __restrict__ x,
                             __nv_bfloat16* __restrict__ xb)
{
    int bn = blockIdx.x;
    int b  = bn >> 10;
    int n  = bn & 1023;
    const float* src;
    if (n < Ee)            src = ent_table + (size_t)ents[b * Ee + n] * Hd;
    else if (n < Ee + Rr)  src = rel_table + (size_t)rels[b * Rr + (n - Ee)] * Hd;
    else                   src = rel_table + (size_t)ROOTI * Hd;
    float v = src[threadIdx.x];
    size_t idx = (size_t)bn * Hd + threadIdx.x;
    x[idx]  = v;
    xb[idx] = __float2bfloat16(v);
}

// ---------------------------------------------------------------------------
__global__ void packqkv_kernel(const float* __restrict__ wq,
                               const float* __restrict__ wk,
                               const float* __restrict__ wv,
                               __nv_bfloat16* __restrict__ out)
{
    int j = blockIdx.y;
    int i = blockIdx.x * 256 + threadIdx.x;
    int k = i / 768, c = i - k * 768;
    const float* base;
    int cc;
    if (c < 256)      { base = wq; cc = c; }
    else if (c < 512) { base = wk; cc = c - 256; }
    else              { base = wv; cc = c - 512; }
    out[(size_t)j * 196608 + i] =
        __float2bfloat16(base[(size_t)j * 65536 + k * 256 + cc]);
}

__global__ void cvt_bf_kernel(const float* __restrict__ in,
                              __nv_bfloat16* __restrict__ out)
{
    int i = blockIdx.x * 256 + threadIdx.x;
    out[i] = __float2bfloat16(in[i]);
}

// ---------------------------------------------------------------------------
__global__ void adjpack_kernel(const int* __restrict__ adj,
                               unsigned* __restrict__ adjb)
{
    int gw   = blockIdx.x * 8 + (threadIdx.x >> 5);
    int lane = threadIdx.x & 31;
    int row  = gw >> 5;
    int wrd  = gw & 31;
    int v = adj[((size_t)row << 10) + wrd * 32 + lane];
    unsigned m = __ballot_sync(0xffffffffu, v != 0);
    if (lane == 0) adjb[gw] = m;
}

// ---------------------------------------------------------------------------
// bf16 GEMM: 128x128 block, 8 warps (2x4), warp 64x32, k16 stages.
// A smem row-major [m][12 words] via cp.async; B smem [kw][136] via prmt.
// ---------------------------------------------------------------------------
#define GA_STG 1536        // words: 128 * 12
#define GB_STG 1088        // words: 8 * 136

__global__ void __launch_bounds__(256, 2)
gemm_tc(const __nv_bfloat16* __restrict__ A,
        const __nv_bfloat16* __restrict__ W,
        float* __restrict__ Cf,
        __nv_bfloat16* __restrict__ Cb,
        int K, int lda, int ldb, int ldc,
        const float* __restrict__ bias,
        const float* __restrict__ alpha,
        int mode)
{
    __shared__ __align__(16) unsigned sm[2 * GA_STG + 2 * GB_STG];
    unsigned* Bsm = sm + 2 * GA_STG;
    unsigned sbase = (unsigned)__cvta_generic_to_shared(sm);

    int t    = threadIdx.x;
    int w    = t >> 5, lane = t & 31;
    int gid  = lane >> 2, tid4 = lane & 3;
    int wm0  = (w >> 2) * 64;
    int wn0  = (w & 3) * 32;
    int row0 = blockIdx.y << 7;
    int col0 = blockIdx.x << 7;

    int am  = t >> 1;            // A row 0..127
    int aw0 = (t & 1) * 4;       // A word offset 0/4
    int bkw = t >> 5;            // B word row 0..7
    int bn4 = (t & 31) * 4;      // B col words

    const __nv_bfloat16* Ap  = A + (size_t)(row0 + am) * lda + aw0 * 2;
    const __nv_bfloat16* Bp0 = W + (size_t)(bkw * 2) * ldb + col0 + bn4;
    const __nv_bfloat16* Bp1 = Bp0 + ldb;

    unsigned aDst = sbase + (am * 12 + aw0) * 4;   // byte addr, stage 0

    // preload stage 0
    cpasync16(aDst, Ap);
    CP_COMMIT;
    {
        uint2 u = *(const uint2*)Bp0;
        uint2 v = *(const uint2*)Bp1;
        *(uint4*)&Bsm[bkw * 136 + bn4] =
            make_uint4(prmt(u.x, v.x, 0x5410), prmt(u.x, v.x, 0x7632),
                       prmt(u.y, v.y, 0x5410), prmt(u.y, v.y, 0x7632));
    }
    CP_WAIT0;
    __syncthreads();

    float acc[4][4][4] = {};
    int buf = 0;

    for (int k0 = 16; k0 <= K; k0 += 16) {
        uint2 nu, nv;
        if (k0 < K) {
            // async A into next buffer (safe: consumed two syncs ago)
            cpasync16(aDst + (buf ^ 1) * (GA_STG * 4), Ap + k0);
            CP_COMMIT;
            nu = *(const uint2*)(Bp0 + (size_t)k0 * ldb);
            nv = *(const uint2*)(Bp1 + (size_t)k0 * ldb);
        }
        {
            const unsigned* Ab = sm + buf * GA_STG;
            const unsigned* Bb = Bsm + buf * GB_STG;
            unsigned af[4][4], bfr[4][2];
#pragma unroll
            for (int nt = 0; nt < 4; nt++) {
                bfr[nt][0] = Bb[tid4 * 136 + wn0 + nt * 8 + gid];
                bfr[nt][1] = Bb[(tid4 + 4) * 136 + wn0 + nt * 8 + gid];
            }
#pragma unroll
            for (int mt = 0; mt < 4; mt++) {
                int r = wm0 + mt * 16 + gid;
                af[mt][0] = Ab[r * 12 + tid4];
                af[mt][1] = Ab[(r + 8) * 12 + tid4];
                af[mt][2] = Ab[r * 12 + tid4 + 4];
                af[mt][3] = Ab[(r + 8) * 12 + tid4 + 4];
            }
#pragma unroll
            for (int mt = 0; mt < 4; mt++)
#pragma unroll
                for (int nt = 0; nt < 4; nt++)
                    BF16_MMA(acc[mt][nt], af[mt], bfr[nt]);
        }
        if (k0 < K) {
            buf ^= 1;
            *(uint4*)&Bsm[buf * GB_STG + bkw * 136 + bn4] =
                make_uint4(prmt(nu.x, nv.x, 0x5410), prmt(nu.x, nv.x, 0x7632),
                           prmt(nu.y, nv.y, 0x5410), prmt(nu.y, nv.y, 0x7632));
            CP_WAIT0;
            __syncthreads();
        }
    }

#pragma unroll
    for (int mt = 0; mt < 4; mt++) {
        int r0 = row0 + wm0 + mt * 16 + gid;
#pragma unroll
        for (int nt = 0; nt < 4; nt++) {
            int c = col0 + wn0 + nt * 8 + 2 * tid4;
            float v0 = acc[mt][nt][0], v1 = acc[mt][nt][1];
            float v2 = acc[mt][nt][2], v3 = acc[mt][nt][3];
            if (mode != 0) {
                float b0v = bias[c], b1v = bias[c + 1];
                v0 += b0v; v1 += b1v; v2 += b0v; v3 += b1v;
            }
            if (mode == 1) {
                float a0v = alpha[c], a1v = alpha[c + 1];
                v0 = v0 >= 0.f ? v0 : a0v * v0;
                v1 = v1 >= 0.f ? v1 : a1v * v1;
                v2 = v2 >= 0.f ? v2 : a0v * v2;
                v3 = v3 >= 0.f ? v3 : a1v * v3;
            }
            if (Cf) {
                *(float2*)&Cf[(size_t)r0 * ldc + c]       = make_float2(v0, v1);
                *(float2*)&Cf[(size_t)(r0 + 8) * ldc + c] = make_float2(v2, v3);
            } else {
                *(unsigned*)&Cb[(size_t)r0 * ldc + c]       = packbf(v0, v1);
                *(unsigned*)&Cb[(size_t)(r0 + 8) * ldc + c] = packbf(v2, v3);
            }
        }
    }
}

// ---------------------------------------------------------------------------
// Fused flash attention. Q/K row-major [row][36 words] via cp.async,
// V [jw][72] prmt, P [cw][136]. All fragment loads bank-conflict-free.
// ---------------------------------------------------------------------------
#define FL_QS   0
#define FL_KS   4608                 // 128*36
#define FL_VS   (FL_KS + 4608)
#define FL_PS   (FL_VS + 64 * 72)
#define FL_RED  (FL_PS + 64 * 136)
#define FL_SMEM ((FL_RED + 2 * 4 * 128) * 4)

__global__ void __launch_bounds__(256, 2)
flash_attn(const __nv_bfloat16* __restrict__ qkv,
           const unsigned* __restrict__ adjb,
           const float* __restrict__ X,
           float* __restrict__ O)
{
    extern __shared__ __align__(16) unsigned sm[];
    unsigned sbase = (unsigned)__cvta_generic_to_shared(sm);
    unsigned* Qs = sm + FL_QS;
    unsigned* Ks = sm + FL_KS;
    unsigned* Vs = sm + FL_VS;
    unsigned* Ps = sm + FL_PS;
    float* redm = (float*)(sm + FL_RED);
    float* reds = redm + 4 * 128;

    int t = threadIdx.x;
    int w = t >> 5, lane = t & 31;
    int gid = lane >> 2, tid4 = lane & 3;
    int wm0 = (w >> 2) * 64;
    int wn0 = (w & 3) * 32;
    int wd0 = (w & 3) * 16;
    int z = blockIdx.y;
    int b = z >> 2, h = z & 3;
    int i0 = blockIdx.x << 7;

    int cprow = t >> 1;            // 0..127
    int cpw0  = (t & 1) * 16;      // word offset 0/16

    // ---- Q tile (row-major, cp.async), once ----
    {
        const __nv_bfloat16* src = qkv + (size_t)(b * Nn + i0 + cprow) * 768
                                 + h * 64 + cpw0 * 2;
        unsigned dst = sbase + (FL_QS + cprow * 36 + cpw0) * 4;
        cpasync16(dst,      src);
        cpasync16(dst + 16, src + 8);
        cpasync16(dst + 32, src + 16);
        cpasync16(dst + 48, src + 24);
        CP_COMMIT;
    }

    float m_st[8], l_st[8];
    float oac[4][2][4] = {};
#pragma unroll
    for (int s = 0; s < 8; s++) { m_st[s] = -1e4f; l_st[s] = 0.f; }

    for (int jt = 0; jt < 8; jt++) {
        int j0 = jt << 7;
        __syncthreads();   // previous iter's reads of Ks/Vs/Ps complete

        // ---- K tile (row-major, cp.async) ----
        {
            const __nv_bfloat16* src = qkv + (size_t)(b * Nn + j0 + cprow) * 768
                                     + 256 + h * 64 + cpw0 * 2;
            unsigned dst = sbase + (FL_KS + cprow * 36 + cpw0) * 4;
            cpasync16(dst,      src);
            cpasync16(dst + 16, src + 8);
            cpasync16(dst + 32, src + 16);
            cpasync16(dst + 48, src + 24);
            CP_COMMIT;
        }
        // ---- V tile: Vs[jw][d] (j-pair words via prmt) ----
        {
            int jw = t >> 2;
            int d0 = (t & 3) * 16;
            const __nv_bfloat16* r0 = qkv + (size_t)(b * Nn + j0 + 2 * jw) * 768
                                    + 512 + h * 64 + d0;
            const __nv_bfloat16* r1 = r0 + 768;
            uint4 ua = *(const uint4*)r0;
            uint4 ub = *(const uint4*)(r0 + 8);
            uint4 va = *(const uint4*)r1;
            uint4 vb = *(const uint4*)(r1 + 8);
            unsigned* dst = &Vs[jw * 72 + d0];
            *(uint4*)(dst)      = make_uint4(prmt(ua.x, va.x, 0x5410),
                                             prmt(ua.x, va.x, 0x7632),
                                             prmt(ua.y, va.y, 0x5410),
                                             prmt(ua.y, va.y, 0x7632));
            *(uint4*)(dst + 4)  = make_uint4(prmt(ua.z, va.z, 0x5410),
                                             prmt(ua.z, va.z, 0x7632),
                                             prmt(ua.w, va.w, 0x5410),
                                             prmt(ua.w, va.w, 0x7632));
            *(uint4*)(dst + 8)  = make_uint4(prmt(ub.x, vb.x, 0x5410),
                                             prmt(ub.x, vb.x, 0x7632),
                                             prmt(ub.y, vb.y, 0x5410),
                                             prmt(ub.y, vb.y, 0x7632));
            *(uint4*)(dst + 12) = make_uint4(prmt(ub.z, vb.z, 0x5410),
                                             prmt(ub.z, vb.z, 0x7632),
                                             prmt(ub.w, vb.w, 0x5410),
                                             prmt(ub.w, vb.w, 0x7632));
        }
        CP_WAIT0;
        __syncthreads();

        // ---- S = Q @ K^T (128x128, d=64 -> 32 words) ----
        float sac[4][4][4] = {};
#pragma unroll
        for (int kc = 0; kc < 32; kc += 8) {
            unsigned af[4][4], bfr[4][2];
#pragma unroll
            for (int nt = 0; nt < 4; nt++) {
                int jr = (wn0 + nt * 8 + gid) * 36;
                bfr[nt][0] = Ks[jr + kc + tid4];
                bfr[nt][1] = Ks[jr + kc + tid4 + 4];
            }
#pragma unroll
            for (int mt = 0; mt < 4; mt++) {
                int r = (wm0 + mt * 16 + gid) * 36;
                af[mt][0] = Qs[r + kc + tid4];
                af[mt][1] = Qs[r + 288 + kc + tid4];        // +8 rows
                af[mt][2] = Qs[r + kc + tid4 + 4];
                af[mt][3] = Qs[r + 288 + kc + tid4 + 4];
            }
#pragma unroll
            for (int mt = 0; mt < 4; mt++)
#pragma unroll
                for (int nt = 0; nt < 4; nt++)
                    BF16_MMA(sac[mt][nt], af[mt], bfr[nt]);
        }

        // ---- mask (bitpacked) + scale, per-row tile max ----
        int wq = (j0 + wn0) >> 5;
        float tmax[8];
#pragma unroll
        for (int s = 0; s < 8; s++) tmax[s] = -1e30f;
#pragma unroll
        for (int mt = 0; mt < 4; mt++) {
            int r = i0 + wm0 + mt * 16 + gid;
            unsigned w0 = adjb[(((size_t)(b * Nn + r)) << 5) + wq];
            unsigned w1 = adjb[(((size_t)(b * Nn + r + 8)) << 5) + wq];
#pragma unroll
            for (int nt = 0; nt < 4; nt++) {
                int bit = nt * 8 + 2 * tid4;
                sac[mt][nt][0] = (w0 >> bit) & 1       ? sac[mt][nt][0] * 0.0625f : -1e30f;
                sac[mt][nt][1] = (w0 >> (bit + 1)) & 1 ? sac[mt][nt][1] * 0.0625f : -1e30f;
                sac[mt][nt][2] = (w1 >> bit) & 1       ? sac[mt][nt][2] * 0.0625f : -1e30f;
                sac[mt][nt][3] = (w1 >> (bit + 1)) & 1 ? sac[mt][nt][3] * 0.0625f : -1e30f;
                tmax[mt * 2 + 0] = fmaxf(tmax[mt * 2 + 0],
                                         fmaxf(sac[mt][nt][0], sac[mt][nt][1]));
                tmax[mt * 2 + 1] = fmaxf(tmax[mt * 2 + 1],
                                         fmaxf(sac[mt][nt][2], sac[mt][nt][3]));
            }
        }
#pragma unroll
        for (int s = 0; s < 8; s++) {
            tmax[s] = fmaxf(tmax[s], __shfl_xor_sync(0xffffffffu, tmax[s], 1));
            tmax[s] = fmaxf(tmax[s], __shfl_xor_sync(0xffffffffu, tmax[s], 2));
        }
        if (tid4 == 0) {
#pragma unroll
            for (int mt = 0; mt < 4; mt++) {
                redm[(w & 3) * 128 + wm0 + mt * 16 + gid]     = tmax[mt * 2];
                redm[(w & 3) * 128 + wm0 + mt * 16 + gid + 8] = tmax[mt * 2 + 1];
            }
        }
        __syncthreads();

        float alp[8];
#pragma unroll
        for (int mt = 0; mt < 4; mt++)
#pragma unroll
            for (int q = 0; q < 2; q++) {
                int r = wm0 + mt * 16 + gid + q * 8;
                float tm = fmaxf(fmaxf(redm[r], redm[128 + r]),
                                 fmaxf(redm[256 + r], redm[384 + r]));
                int s = mt * 2 + q;
                float mn = fmaxf(m_st[s], fmaxf(tm, -1e4f));
                alp[s] = __expf(m_st[s] - mn);
                m_st[s] = mn;
            }

        // ---- exp, partial sums, store P (bf16 pairs along j) ----
        float psum[8] = {};
#pragma unroll
        for (int mt = 0; mt < 4; mt++) {
            int r = wm0 + mt * 16 + gid;
            int s0 = mt * 2, s1 = mt * 2 + 1;
#pragma unroll
            for (int nt = 0; nt < 4; nt++) {
                int cw = (wn0 >> 1) + nt * 4 + tid4;
                float e0 = __expf(sac[mt][nt][0] - m_st[s0]);
                float e1 = __expf(sac[mt][nt][1] - m_st[s0]);
                float e2 = __expf(sac[mt][nt][2] - m_st[s1]);
                float e3 = __expf(sac[mt][nt][3] - m_st[s1]);
                psum[s0] += e0 + e1;
                psum[s1] += e2 + e3;
                Ps[cw * 136 + r]     = packbf(e0, e1);
                Ps[cw * 136 + r + 8] = packbf(e2, e3);
            }
        }
#pragma unroll
        for (int s = 0; s < 8; s++) {
            psum[s] += __shfl_xor_sync(0xffffffffu, psum[s], 1);
            psum[s] += __shfl_xor_sync(0xffffffffu, psum[s], 2);
        }
        if (tid4 == 0) {
#pragma unroll
            for (int mt = 0; mt < 4; mt++) {
                reds[(w & 3) * 128 + wm0 + mt * 16 + gid]     = psum[mt * 2];
                reds[(w & 3) * 128 + wm0 + mt * 16 + gid + 8] = psum[mt * 2 + 1];
            }
        }
        __syncthreads();

        // ---- update l, rescale O ----
#pragma unroll
        for (int mt = 0; mt < 4; mt++)
#pragma unroll
            for (int q = 0; q < 2; q++) {
                int r = wm0 + mt * 16 + gid + q * 8;
                int s = mt * 2 + q;
                float ps = reds[r] + reds[128 + r] + reds[256 + r] + reds[384 + r];
                l_st[s] = l_st[s] * alp[s] + ps;
            }
#pragma unroll
        for (int mt = 0; mt < 4; mt++)
#pragma unroll
            for (int nt = 0; nt < 2; nt++) {
                oac[mt][nt][0] *= alp[mt * 2];
                oac[mt][nt][1] *= alp[mt * 2];
                oac[mt][nt][2] *= alp[mt * 2 + 1];
                oac[mt][nt][3] *= alp[mt * 2 + 1];
            }

        // ---- O += P @ V (128x64, k=128 -> 64 words) ----
#pragma unroll
        for (int ko = 0; ko < 64; ko += 8) {
            unsigned af[4][4], bfr[2][2];
#pragma unroll
            for (int nt = 0; nt < 2; nt++) {
                bfr[nt][0] = Vs[(ko + tid4) * 72 + wd0 + nt * 8 + gid];
                bfr[nt][1] = Vs[(ko + tid4 + 4) * 72 + wd0 + nt * 8 + gid];
            }
#pragma unroll
            for (int mt = 0; mt < 4; mt++) {
                af[mt][0] = Ps[(ko + tid4) * 136 + wm0 + mt * 16 + gid];
                af[mt][1] = Ps[(ko + tid4) * 136 + wm0 + mt * 16 + gid + 8];
                af[mt][2] = Ps[(ko + tid4 + 4) * 136 + wm0 + mt * 16 + gid];
                af[mt][3] = Ps[(ko + tid4 + 4) * 136 + wm0 + mt * 16 + gid + 8];
            }
#pragma unroll
            for (int mt = 0; mt < 4; mt++)
#pragma unroll
                for (int nt = 0; nt < 2; nt++)
                    BF16_MMA(oac[mt][nt], af[mt], bfr[nt]);
        }
    }

    // ---- epilogue: O/l + residual X ----
    float inv[8];
#pragma unroll
    for (int s = 0; s < 8; s++) inv[s] = 1.f / l_st[s];
#pragma unroll
    for (int mt = 0; mt < 4; mt++) {
        int r = i0 + wm0 + mt * 16 + gid;
#pragma unroll
        for (int nt = 0; nt < 2; nt++) {
            int c = wd0 + nt * 8 + 2 * tid4;
            size_t idx0 = (size_t)(b * Nn + r) * Hd + h * 64 + c;
            size_t idx1 = (size_t)(b * Nn + r + 8) * Hd + h * 64 + c;
            float2 x0 = *(const float2*)&X[idx0];
            float2 x1 = *(const float2*)&X[idx1];
            *(float2*)&O[idx0] = make_float2(oac[mt][nt][0] * inv[mt * 2] + x0.x,
                                             oac[mt][nt][1] * inv[mt * 2] + x0.y);
            *(float2*)&O[idx1] = make_float2(oac[mt][nt][2] * inv[mt * 2 + 1] + x1.x,
                                             oac[mt][nt][3] * inv[mt * 2 + 1] + x1.y);
        }
    }
}

// ---------------------------------------------------------------------------
__global__ void ln_kernel(const float* __restrict__ A,
                          const float* __restrict__ Badd,
                          const float* __restrict__ gamma,
                          const float* __restrict__ beta,
                          float* __restrict__ out,
                          __nv_bfloat16* __restrict__ outb)
{
    int row  = (blockIdx.x * blockDim.x + threadIdx.x) >> 5;
    int lane = threadIdx.x & 31;
    size_t base = (size_t)row * Hd + lane * 8;

    float4 v0 = *(const float4*)&A[base];
    float4 v1 = *(const float4*)&A[base + 4];
    if (Badd) {
        float4 b0 = *(const float4*)&Badd[base];
        float4 b1 = *(const float4*)&Badd[base + 4];
        v0.x += b0.x; v0.y += b0.y; v0.z += b0.z; v0.w += b0.w;
        v1.x += b1.x; v1.y += b1.y; v1.z += b1.z; v1.w += b1.w;
    }

    float s = v0.x + v0.y + v0.z + v0.w + v1.x + v1.y + v1.z + v1.w;
#pragma unroll
    for (int off = 16; off > 0; off >>= 1)
        s += __shfl_xor_sync(0xffffffffu, s, off);
    float mean = s * (1.f / Hd);

    float d0x = v0.x - mean, d0y = v0.y - mean, d0z = v0.z - mean, d0w = v0.w - mean;
    float d1x = v1.x - mean, d1y = v1.y - mean, d1z = v1.z - mean, d1w = v1.w - mean;
    float q = d0x * d0x + d0y * d0y + d0z * d0z + d0w * d0w
            + d1x * d1x + d1y * d1y + d1z * d1z + d1w * d1w;
#pragma unroll
    for (int off = 16; off > 0; off >>= 1)
        q += __shfl_xor_sync(0xffffffffu, q, off);
    float rstd = rsqrtf(q * (1.f / Hd) + 1e-5f);

    int c = lane * 8;
    float4 g0 = *(const float4*)&gamma[c];
    float4 g1 = *(const float4*)&gamma[c + 4];
    float4 b0 = *(const float4*)&beta[c];
    float4 b1 = *(const float4*)&beta[c + 4];
    float o0 = d0x * rstd * g0.x + b0.x;
    float o1 = d0y * rstd * g0.y + b0.y;
    float o2 = d0z * rstd * g0.z + b0.z;
    float o3 = d0w * rstd * g0.w + b0.w;
    float o4 = d1x * rstd * g1.x + b1.x;
    float o5 = d1y * rstd * g1.y + b1.y;
    float o6 = d1z * rstd * g1.z + b1.z;
    float o7 = d1w * rstd * g1.w + b1.w;
    *(float4*)&out[base]     = make_float4(o0, o1, o2, o3);
    *(float4*)&out[base + 4] = make_float4(o4, o5, o6, o7);
    if (outb) {
        *(uint4*)&outb[base] = make_uint4(packbf(o0, o1), packbf(o2, o3),
                                          packbf(o4, o5), packbf(o6, o7));
    }
}

// ---------------------------------------------------------------------------
__global__ void fill_tail_kernel(float* __restrict__ out, int start, int total)
{
    int i = blockIdx.x * blockDim.x + threadIdx.x + start;
    if (i < total) out[i] = 1.0f;
}

// ---------------------------------------------------------------------------
extern "C" void kernel_launch(void* const* d_in, const int* in_sizes, int n_in,
                              void* d_out, int out_size)
{
    const int*   ents      = (const int*)  d_in[0];
    const int*   rels      = (const int*)  d_in[1];
    const int*   adjs      = (const int*)  d_in[2];
    const float* ent_table = (const float*)d_in[3];
    const float* rel_table = (const float*)d_in[4];
    const float* Wq        = (const float*)d_in[5];
    const float* Wk        = (const float*)d_in[6];
    const float* Wv        = (const float*)d_in[7];
    const float* l1w       = (const float*)d_in[8];
    const float* l1b       = (const float*)d_in[9];
    const float* l2w       = (const float*)d_in[10];
    const float* l2b       = (const float*)d_in[11];
    const float* ln_g      = (const float*)d_in[12];
    const float* ln_b      = (const float*)d_in[13];
    const float* alpha     = (const float*)d_in[14];
    float* out = (float*)d_out;

    float *x, *o, *tb, *h2;
    __nv_bfloat16 *xb, *qkvb, *tbb, *h1b, *wqkvb, *w1b, *w2b;
    unsigned* adjb;
    cudaGetSymbolAddress((void**)&x,     g_x);
    cudaGetSymbolAddress((void**)&xb,    g_xb);
    cudaGetSymbolAddress((void**)&qkvb,  g_qkvb);
    cudaGetSymbolAddress((void**)&o,     g_o);
    cudaGetSymbolAddress((void**)&tb,    g_t);
    cudaGetSymbolAddress((void**)&tbb,   g_tb);
    cudaGetSymbolAddress((void**)&h2,    g_h2);
    cudaGetSymbolAddress((void**)&h1b,   g_h1b);
    cudaGetSymbolAddress((void**)&wqkvb, g_wqkvb);
    cudaGetSymbolAddress((void**)&w1b,   g_w1b);
    cudaGetSymbolAddress((void**)&w2b,   g_w2b);
    cudaGetSymbolAddress((void**)&adjb,  g_adjb);

    cudaFuncSetAttribute(flash_attn, cudaFuncAttributeMaxDynamicSharedMemorySize,
                         FL_SMEM);

    embed_kernel<<<Bsz * Nn, 256>>>(ents, rels, ent_table, rel_table, x, xb);
    adjpack_kernel<<<Bsz * Nn * 32 / 8, 256>>>(adjs, adjb);
    packqkv_kernel<<<dim3(768, 2), 256>>>(Wq, Wk, Wv, wqkvb);
    cvt_bf_kernel<<<2 * Hd * 4 * Hd / 256, 256>>>(l1w, w1b);
    cvt_bf_kernel<<<2 * 4 * Hd * Hd / 256, 256>>>(l2w, w2b);

    for (int j = 0; j < 2; j++) {
        const __nv_bfloat16* wqkv = wqkvb + (size_t)j * Hd * 3 * Hd;
        const __nv_bfloat16* w1   = w1b   + (size_t)j * Hd * 4 * Hd;
        const __nv_bfloat16* w2   = w2b   + (size_t)j * 4 * Hd * Hd;
        const float* b1 = l1b + (size_t)j * 4 * Hd;
        const float* b2 = l2b + (size_t)j * Hd;
        const float* lg = ln_g + (size_t)j * Hd;
        const float* lb = ln_b + (size_t)j * Hd;
        const float* al = alpha + (size_t)j * 4 * Hd;

        gemm_tc<<<dim3(6, 128), 256>>>(xb, wqkv, nullptr, qkvb,
                                       Hd, Hd, 768, 768, nullptr, nullptr, 0);

        flash_attn<<<dim3(8, Bsz * 4), 256, FL_SMEM>>>(qkvb, adjb, x, o);

        ln_kernel<<<Mrows / 8, 256>>>(o, nullptr, lg, lb, tb, tbb);

        gemm_tc<<<dim3(8, 128), 256>>>(tbb, w1, nullptr, h1b,
                                       Hd, Hd, 4 * Hd, 4 * Hd, b1, al, 1);
        gemm_tc<<<dim3(2, 128), 256>>>(h1b, w2, h2, nullptr,
                                       4 * Hd, 4 * Hd, Hd, Hd, b2, nullptr, 2);

        if (j == 0)
            ln_kernel<<<Mrows / 8, 256>>>(h2, tb, lg, lb, x, xb);
        else
            ln_kernel<<<Mrows / 8, 256>>>(h2, tb, lg, lb, out, nullptr);
    }

    int tail = out_size - XSZ;
    if (tail > 0)
        fill_tail_kernel<<<(tail + 255) / 256, 256>>>(out, XSZ, out_size);
}